// round 4
// baseline (speedup 1.0000x reference)
#include <cuda_runtime.h>
#include <math.h>

// Problem constants
#define B_    32
#define C_    256
#define L_    8192
#define H_    16
#define ROWS  (B_ * C_)        // 8192 rows
#define L4    (L_ / 4)         // 2048 float4 per row
#define GB_   4                // batches per group (32 MiB per group)
#define NG_   (B_ / GB_)       // 8 groups
#define RG_   (GB_ * C_)       // 1024 rows per group

// Scratch (allocation-free rule: __device__ globals)
__device__ float d_y[ROWS];    // per-(b,c) means

// ---------------------------------------------------------------------------
// Mean role: one block sums one row (2048 float4). Default cache policy so the
// lines persist in L2 for the NEXT kernel's scale pass.
// ---------------------------------------------------------------------------
__device__ __forceinline__ void mean_role(const float4* __restrict__ x, int row) {
    const float4* __restrict__ p = x + (size_t)row * L4;
    float s = 0.0f;
    #pragma unroll 8
    for (int i = threadIdx.x; i < L4; i += 256) {
        float4 v = __ldcg(p + i);
        s += (v.x + v.y) + (v.z + v.w);
    }
    #pragma unroll
    for (int off = 16; off > 0; off >>= 1)
        s += __shfl_xor_sync(0xFFFFFFFFu, s, off);

    __shared__ float warp_sums[8];
    const int lane = threadIdx.x & 31;
    const int wid  = threadIdx.x >> 5;
    if (lane == 0) warp_sums[wid] = s;
    __syncthreads();
    if (wid == 0) {
        float t = (lane < 8) ? warp_sums[lane] : 0.0f;
        #pragma unroll
        for (int off = 4; off > 0; off >>= 1)
            t += __shfl_xor_sync(0xFFFFFFFFu, t, off);
        if (lane == 0) d_y[row] = t * (1.0f / (float)L_);
    }
}

// ---------------------------------------------------------------------------
// Scale role: block recomputes the tiny MLP for its row's batch (redundant,
// ~1us, removes excite kernels + a global sync), then streams the row:
// read x via __ldcs (last use, evict-first) * gate -> __stcs (don't pollute L2).
// ---------------------------------------------------------------------------
__device__ __forceinline__ void scale_role(const float4* __restrict__ x,
                                           float4* __restrict__ out,
                                           const float* __restrict__ W1,
                                           const float* __restrict__ W2,
                                           int row) {
    const int b = row >> 8;      // row / C_
    const int c = row & 255;     // row % C_
    const int t = threadIdx.x;

    __shared__ float ys[C_];
    __shared__ float hs[H_];
    __shared__ float gate_s;

    ys[t] = d_y[b * C_ + t];
    __syncthreads();

    // h[hh] = relu( y . W1[hh,:] ) — 16 lanes per h, 16 MACs each, shfl-reduce
    {
        const int hh = t >> 4;          // 0..15
        const int k  = t & 15;          // 0..15
        const float* __restrict__ w1 = W1 + hh * C_ + k * 16;
        const float* __restrict__ yy = ys + k * 16;
        float s = 0.0f;
        #pragma unroll
        for (int i = 0; i < 16; ++i) s += yy[i] * w1[i];
        #pragma unroll
        for (int off = 8; off > 0; off >>= 1)
            s += __shfl_down_sync(0xFFFFFFFFu, s, off, 16);
        if (k == 0) hs[hh] = fmaxf(s, 0.0f);
    }
    __syncthreads();

    if (t == 0) {
        float a = 0.0f;
        const float* __restrict__ w2 = W2 + c * H_;
        #pragma unroll
        for (int j = 0; j < H_; ++j) a += hs[j] * w2[j];
        gate_s = 1.0f / (1.0f + expf(-a));
    }
    __syncthreads();
    const float gv = gate_s;

    const float4* __restrict__ px = x   + (size_t)row * L4;
    float4* __restrict__       po = out + (size_t)row * L4;
    #pragma unroll 8
    for (int i = t; i < L4; i += 256) {
        float4 v = __ldcs(px + i);
        v.x *= gv; v.y *= gv; v.z *= gv; v.w *= gv;
        __stcs(po + i, v);
    }
}

// ---------------------------------------------------------------------------
// Kernels: prologue mean, pipelined fused (scale g || mean g+1), tail scale.
// ---------------------------------------------------------------------------
__global__ __launch_bounds__(256) void se_mean_k(const float4* __restrict__ x, int g) {
    mean_role(x, g * RG_ + blockIdx.x);
}

__global__ __launch_bounds__(256) void se_fused_k(const float4* __restrict__ x,
                                                  float4* __restrict__ out,
                                                  const float* __restrict__ W1,
                                                  const float* __restrict__ W2,
                                                  int sg, int mg) {
    const int r = blockIdx.x >> 1;
    if (blockIdx.x & 1) mean_role(x, mg * RG_ + r);
    else                scale_role(x, out, W1, W2, sg * RG_ + r);
}

__global__ __launch_bounds__(256) void se_scale_k(const float4* __restrict__ x,
                                                  float4* __restrict__ out,
                                                  const float* __restrict__ W1,
                                                  const float* __restrict__ W2,
                                                  int sg) {
    scale_role(x, out, W1, W2, sg * RG_ + blockIdx.x);
}

// ---------------------------------------------------------------------------
extern "C" void kernel_launch(void* const* d_in, const int* in_sizes, int n_in,
                              void* d_out, int out_size) {
    const float4* x  = (const float4*)d_in[0];
    const float*  W1 = (const float*)d_in[1];
    const float*  W2 = (const float*)d_in[2];
    float4* out = (float4*)d_out;

    se_mean_k<<<RG_, 256>>>(x, 0);
    for (int g = 0; g < NG_ - 1; ++g)
        se_fused_k<<<2 * RG_, 256>>>(x, out, W1, W2, g, g + 1);
    se_scale_k<<<RG_, 256>>>(x, out, W1, W2, NG_ - 1);
}

// round 5
// speedup vs baseline: 1.5031x; 1.5031x over previous
#include <cuda_runtime.h>
#include <math.h>

// Problem constants
#define B_   32
#define C_   256
#define L_   8192
#define H_   16
#define ROWS (B_ * C_)            // 8192 (b,c) rows
#define L4   (L_ / 4)             // 2048 float4 per row
#define ITER 8                    // 2048 / 256 threads

// Scratch (allocation-free rule: __device__ globals)
__device__ float d_y[ROWS];   // per-(b,c) means
__device__ float d_g[ROWS];   // per-(b,c) gates

// ---------------------------------------------------------------------------
// K1: mean over L per row. One block per row (ascending), 256 threads,
// float4 loads, default L2 allocation so the TAIL of the stream stays
// resident in L2 for K3's reverse-order pass.
// ---------------------------------------------------------------------------
__global__ __launch_bounds__(256) void se_mean_kernel(const float4* __restrict__ x) {
    const int row = blockIdx.x;
    const float4* __restrict__ p = x + (size_t)row * L4;

    float s = 0.0f;
    #pragma unroll
    for (int i = 0; i < ITER; ++i) {
        float4 v = __ldg(p + threadIdx.x + i * 256);
        s += (v.x + v.y) + (v.z + v.w);
    }

    #pragma unroll
    for (int off = 16; off > 0; off >>= 1)
        s += __shfl_xor_sync(0xFFFFFFFFu, s, off);

    __shared__ float warp_sums[8];
    const int lane = threadIdx.x & 31;
    const int wid  = threadIdx.x >> 5;
    if (lane == 0) warp_sums[wid] = s;
    __syncthreads();

    if (wid == 0) {
        float t = (lane < 8) ? warp_sums[lane] : 0.0f;
        #pragma unroll
        for (int off = 4; off > 0; off >>= 1)
            t += __shfl_xor_sync(0xFFFFFFFFu, t, off);
        if (lane == 0) d_y[row] = t * (1.0f / (float)L_);
    }
}

// ---------------------------------------------------------------------------
// K2: excite MLP. One block per batch (32 blocks, 256 threads).
// h[j] = relu(sum_c y[c] * W1[j*C + c]);  g[c] = sigmoid(sum_j h[j] * W2[c*H + j])
// ---------------------------------------------------------------------------
__global__ __launch_bounds__(256) void se_excite_kernel(const float* __restrict__ W1,
                                                        const float* __restrict__ W2) {
    const int b = blockIdx.x;
    const int t = threadIdx.x;
    __shared__ float ys[C_];
    __shared__ float hs[H_];

    ys[t] = d_y[b * C_ + t];
    __syncthreads();

    // h: 16 lanes per hidden unit, 16 MACs each, segmented shfl reduce
    {
        const int hh = t >> 4;
        const int k  = t & 15;
        const float* __restrict__ w1 = W1 + hh * C_ + k * 16;
        const float* __restrict__ yy = ys + k * 16;
        float s = 0.0f;
        #pragma unroll
        for (int i = 0; i < 16; ++i) s += yy[i] * w1[i];
        #pragma unroll
        for (int off = 8; off > 0; off >>= 1)
            s += __shfl_down_sync(0xFFFFFFFFu, s, off, 16);
        if (k == 0) hs[hh] = fmaxf(s, 0.0f);
    }
    __syncthreads();

    float s = 0.0f;
    const float* __restrict__ w2 = W2 + t * H_;
    #pragma unroll
    for (int j = 0; j < H_; ++j) s += hs[j] * w2[j];
    d_g[b * C_ + t] = 1.0f / (1.0f + expf(-s));
}

// ---------------------------------------------------------------------------
// K3: out = x * g[row]. One block per row, DESCENDING row order so the first
// waves re-read the x lines still L2-resident from K1's tail. 8 batched
// __ldcs loads (MLP=8), then 8 __stcs stores (evict-first: don't let the
// output stream evict the x tail we're about to read).
// ---------------------------------------------------------------------------
__global__ __launch_bounds__(256) void se_scale_kernel(const float4* __restrict__ x,
                                                       float4* __restrict__ out) {
    const int row = (ROWS - 1) - (int)blockIdx.x;
    const float gv = __ldg(&d_g[row]);

    const float4* __restrict__ px = x   + (size_t)row * L4 + threadIdx.x;
    float4* __restrict__       po = out + (size_t)row * L4 + threadIdx.x;

    float4 v[ITER];
    #pragma unroll
    for (int i = 0; i < ITER; ++i)
        v[i] = __ldcs(px + i * 256);

    #pragma unroll
    for (int i = 0; i < ITER; ++i) {
        v[i].x *= gv; v[i].y *= gv; v[i].z *= gv; v[i].w *= gv;
        __stcs(po + i * 256, v[i]);
    }
}

// ---------------------------------------------------------------------------
extern "C" void kernel_launch(void* const* d_in, const int* in_sizes, int n_in,
                              void* d_out, int out_size) {
    const float4* x  = (const float4*)d_in[0];
    const float*  W1 = (const float*)d_in[1];
    const float*  W2 = (const float*)d_in[2];
    float4* out = (float4*)d_out;

    se_mean_kernel<<<ROWS, 256>>>(x);
    se_excite_kernel<<<B_, 256>>>(W1, W2);
    se_scale_kernel<<<ROWS, 256>>>(x, out);
}